// round 16
// baseline (speedup 1.0000x reference)
#include <cuda_runtime.h>
#include <cuda_fp16.h>
#include <cstdint>

#define BB 4
#define LL 2048
#define EE 1024
#define HH 16
#define DD 64
#define NQKV 4096   // merged QKV output columns: 2048 q|gate, 1024 k, 1024 v

// ---------------- scratch ----------------------------------------------------
__device__ float d_qkv_buf[(size_t)BB * LL * NQKV];        // merged f32 QKV out
__device__ __half d_h16   [(size_t)BB * LL * EE];          // fp16 h
__device__ __half d_wqkv16t[(size_t)NQKV * EE];            // [N][K] fp16 (wq|wk|wv)
__device__ __half d_wo16t [(size_t)EE * HH * DD];
__device__ __half d_q16   [(size_t)BB * LL * HH * DD];     // normed+rope q * 0.125
__device__ __half d_k16   [(size_t)BB * LL * HH * DD];     // normed+rope k
__device__ __half d_vt16  [(size_t)BB * HH * DD * LL];     // V^T per head: [b,h,d,l]
__device__ __half d_ao16  [(size_t)BB * LL * HH * DD];     // gated attn out fp16

// ---------------- helpers ----------------------------------------------------
__device__ __forceinline__ void mma_f16(float* d,
    uint32_t a0, uint32_t a1, uint32_t a2, uint32_t a3,
    uint32_t b0, uint32_t b1)
{
    asm("mma.sync.aligned.m16n8k16.row.col.f32.f16.f16.f32 "
        "{%0,%1,%2,%3}, {%4,%5,%6,%7}, {%8,%9}, {%0,%1,%2,%3};"
        : "+f"(d[0]), "+f"(d[1]), "+f"(d[2]), "+f"(d[3])
        : "r"(a0), "r"(a1), "r"(a2), "r"(a3), "r"(b0), "r"(b1));
}

__device__ __forceinline__ uint32_t smem_u32(const void* p) {
    uint32_t a;
    asm("{ .reg .u64 t; cvta.to.shared.u64 t, %1; cvt.u32.u64 %0, t; }" : "=r"(a) : "l"(p));
    return a;
}

__device__ __forceinline__ uint32_t pack2(float x, float y) {
    __half2 h = __floats2half2_rn(x, y);
    return *(uint32_t*)&h;
}

#define LDSM4(d0, d1, d2, d3, addr) \
    asm volatile("ldmatrix.sync.aligned.m8n8.x4.shared.b16 {%0,%1,%2,%3}, [%4];" \
        : "=r"(d0), "=r"(d1), "=r"(d2), "=r"(d3) : "r"(addr))

#define CP16(dst, src) \
    asm volatile("cp.async.cg.shared.global [%0], [%1], 16;" :: "r"(dst), "l"(src))
#define CP_COMMIT() asm volatile("cp.async.commit_group;")
#define CP_WAIT2()  asm volatile("cp.async.wait_group 2;" ::: "memory")
#define CP_WAIT0()  asm volatile("cp.async.wait_group 0;" ::: "memory")

// ---------------- f32 -> f16 elementwise (8 elems/thread) --------------------
__global__ __launch_bounds__(256) void cvt_h16_kernel(
    const float4* __restrict__ src, uint4* __restrict__ dst, int n8)
{
    int i = blockIdx.x * blockDim.x + threadIdx.x;
    if (i < n8) {
        float4 a = src[2 * i], b = src[2 * i + 1];
        dst[i] = make_uint4(pack2(a.x, a.y), pack2(a.z, a.w),
                            pack2(b.x, b.y), pack2(b.z, b.w));
    }
}

// ---------------- merged weight transpose + cvt (4 matrices, one launch) -----
// z=0: wq->wqkv[0:2048], z=1: wk->wqkv[2048:3072], z=2: wv->wqkv[3072:4096],
// z=3: wo->wo16t. All K=1024 rows in, N cols; out [N][K] fp16.
__global__ __launch_bounds__(256) void transpose_all_kernel(
    const float* __restrict__ wq, const float* __restrict__ wk,
    const float* __restrict__ wv, const float* __restrict__ wo)
{
    __shared__ float sm[32][33];
    const float* in;
    __half* out;
    int N;
    switch (blockIdx.z) {
        case 0: in = wq; out = d_wqkv16t;                      N = 2048; break;
        case 1: in = wk; out = d_wqkv16t + (size_t)2048 * EE;  N = 1024; break;
        case 2: in = wv; out = d_wqkv16t + (size_t)3072 * EE;  N = 1024; break;
        default: in = wo; out = d_wo16t;                       N = 1024; break;
    }
    const int K = EE;
    int n0 = blockIdx.x * 32, k0 = blockIdx.y * 32;
    if (n0 >= N) return;
    int tx = threadIdx.x, ty = threadIdx.y;
#pragma unroll
    for (int i = 0; i < 4; i++)
        sm[ty + i * 8][tx] = in[(size_t)(k0 + ty + i * 8) * N + n0 + tx];
    __syncthreads();
#pragma unroll
    for (int i = 0; i < 4; i++)
        out[(size_t)(n0 + ty + i * 8) * K + k0 + tx] = __float2half(sm[tx][ty + i * 8]);
}

// ---------------- per-head V transpose: qkv v-cols f32 -> vt[b,h,d,l] f16 ----
__global__ __launch_bounds__(256) void vtrans_kernel()
{
    __shared__ float sm[32][33];
    int bh = blockIdx.z;                    // b*16 + h
    int b = bh >> 4, h = bh & 15;
    int d0 = blockIdx.y * 32, l0 = blockIdx.x * 32;
    int tx = threadIdx.x, ty = threadIdx.y;
#pragma unroll
    for (int i = 0; i < 4; i++)
        sm[ty + i * 8][tx] =
            d_qkv_buf[(size_t)(b * LL + l0 + ty + i * 8) * NQKV + 3072 + h * DD + d0 + tx];
    __syncthreads();
#pragma unroll
    for (int i = 0; i < 4; i++)
        d_vt16[((size_t)bh * DD + d0 + ty + i * 8) * LL + l0 + tx] =
            __float2half(sm[tx][ty + i * 8]);
}

// ---------------- fp16 GEMM: C[M,N] = A[M,K] @ Bt[N,K]^T ---------------------
#define GSTR 36
#define GSTAGE_U32 (2 * 128 * GSTR)              // 9216 u32 = 36864 B
#define GEMM_SMEM_BYTES (3 * GSTAGE_U32 * 4)     // 110592 B

__global__ __launch_bounds__(256, 2) void h16_gemm(
    const __half* __restrict__ A, const __half* __restrict__ Bt,
    float* __restrict__ C, int M, int N, int K)
{
    extern __shared__ uint32_t sh[];
    const uint32_t sbase = smem_u32(sh);

    const int tid = threadIdx.x;
    const int lane = tid & 31;
    const int w = tid >> 5;
    const int t = lane & 3;
    const int wm = w & 3;
    const int wn = w >> 2;
    const int rowBase = blockIdx.y * 128;
    const int colBase = blockIdx.x * 128;

    const int q8 = lane >> 3, l8 = lane & 7;
    const uint32_t a_lane = (uint32_t)(((q8 & 1) * 8 + l8) * 144 + (q8 >> 1) * 16);
    const uint32_t b_lane = (uint32_t)(((q8 >> 1) * 8 + l8) * 144 + (q8 & 1) * 16);

    const int crow = tid >> 1;
    const int csb = (tid & 1) * 4;

    const int nch = K / 64;

    auto issue = [&](int c) {
        if (c < nch) {
            const uint32_t st = sbase + (c % 3) * (GSTAGE_U32 * 4);
            const int k0 = c * 64;
#pragma unroll
            for (int i = 0; i < 4; i++)
                CP16(st + crow * 144 + (csb + i) * 16,
                     &A[(size_t)(rowBase + crow) * K + k0 + (csb + i) * 8]);
            const uint32_t bst = st + 128 * 144;
#pragma unroll
            for (int i = 0; i < 4; i++)
                CP16(bst + crow * 144 + (csb + i) * 16,
                     &Bt[(size_t)(colBase + crow) * K + k0 + (csb + i) * 8]);
        }
        CP_COMMIT();
    };

    float acc[2][8][4];
#pragma unroll
    for (int mt = 0; mt < 2; mt++)
#pragma unroll
        for (int nt = 0; nt < 8; nt++)
#pragma unroll
            for (int j = 0; j < 4; j++) acc[mt][nt][j] = 0.f;

    issue(0); issue(1); issue(2);

    for (int c = 0; c < nch; c++) {
        CP_WAIT2();
        __syncthreads();
        const uint32_t st = sbase + (c % 3) * (GSTAGE_U32 * 4);
        const uint32_t abase = st + (uint32_t)(wm * 32) * 144 + a_lane;
        const uint32_t bbase = st + 128 * 144 + (uint32_t)(wn * 64) * 144 + b_lane;

#pragma unroll
        for (int kk = 0; kk < 4; kk++) {
            const uint32_t kb = kk * 32;
            uint32_t a[2][4];
            LDSM4(a[0][0], a[0][1], a[0][2], a[0][3], abase + kb);
            LDSM4(a[1][0], a[1][1], a[1][2], a[1][3], abase + 16 * 144 + kb);
            uint32_t b[8][2];
#pragma unroll
            for (int p = 0; p < 4; p++)
                LDSM4(b[2 * p][0], b[2 * p][1], b[2 * p + 1][0], b[2 * p + 1][1],
                      bbase + (uint32_t)(p * 16) * 144 + kb);
#pragma unroll
            for (int mt = 0; mt < 2; mt++)
#pragma unroll
                for (int nt = 0; nt < 8; nt++)
                    mma_f16(acc[mt][nt], a[mt][0], a[mt][1], a[mt][2], a[mt][3],
                            b[nt][0], b[nt][1]);
        }
        __syncthreads();
        issue(c + 3);
    }

    const int g = lane >> 2;
#pragma unroll
    for (int mt = 0; mt < 2; mt++) {
        int row = rowBase + wm * 32 + mt * 16 + g;
#pragma unroll
        for (int nt = 0; nt < 8; nt++) {
            int col = colBase + wn * 64 + nt * 8 + 2 * t;
            *(float2*)&C[(size_t)row * N + col] = make_float2(acc[mt][nt][0], acc[mt][nt][1]);
            *(float2*)&C[(size_t)(row + 8) * N + col] = make_float2(acc[mt][nt][2], acc[mt][nt][3]);
        }
    }
}

// ---------------- RMSNorm + partial RoPE -> fp16 q/k (q+k per warp) ----------
__global__ __launch_bounds__(256) void norm_rope_kernel(
    const float* __restrict__ cosb, const float* __restrict__ sinb,
    const float* __restrict__ qw, const float* __restrict__ kw)
{
    int row = (blockIdx.x * blockDim.x + threadIdx.x) >> 5;   // (bl, h)
    int lane = threadIdx.x & 31;
    if (row >= BB * LL * HH) return;
    int h = row % HH;
    int bl = row / HH;

    // cos/sin loaded once, shared by q and k
    float c0 = 1.f, s0 = 0.f, c1 = 1.f, s1 = 0.f;
    if (lane < 24) {
        const float* cp = cosb + (size_t)bl * DD;
        const float* sp = sinb + (size_t)bl * DD;
        c0 = cp[lane];      s0 = sp[lane];
        c1 = cp[lane + 32]; s1 = sp[lane + 32];
    }

    // ---- q ----
    {
        const float* ptr = d_qkv_buf + (size_t)bl * NQKV + h * 128;
        float x0 = ptr[lane];
        float x1 = ptr[lane + 32];
        float ss = x0 * x0 + x1 * x1;
#pragma unroll
        for (int o = 16; o; o >>= 1) ss += __shfl_xor_sync(0xffffffffu, ss, o);
        float r = rsqrtf(ss * (1.0f / 64.0f) + 1e-6f);
        x0 = x0 * r * qw[lane];
        x1 = x1 * r * qw[lane + 32];
        float r0 = (x0 * c0 - x1 * s0) * 0.125f;
        float r1 = (x1 * c1 + x0 * s1) * 0.125f;
        __half* dst = d_q16 + ((size_t)bl * HH + h) * DD;
        dst[lane]      = __float2half(r0);
        dst[lane + 32] = __float2half(r1);
    }
    // ---- k ----
    {
        const float* ptr = d_qkv_buf + (size_t)bl * NQKV + 2048 + h * DD;
        float x0 = ptr[lane];
        float x1 = ptr[lane + 32];
        float ss = x0 * x0 + x1 * x1;
#pragma unroll
        for (int o = 16; o; o >>= 1) ss += __shfl_xor_sync(0xffffffffu, ss, o);
        float r = rsqrtf(ss * (1.0f / 64.0f) + 1e-6f);
        x0 = x0 * r * kw[lane];
        x1 = x1 * r * kw[lane + 32];
        float r0 = x0 * c0 - x1 * s0;
        float r1 = x1 * c1 + x0 * s1;
        __half* dst = d_k16 + ((size_t)bl * HH + h) * DD;
        dst[lane]      = __float2half(r0);
        dst[lane + 32] = __float2half(r1);
    }
}

// ---------------- fp16 flash attention, persistent CTAs ----------------------
// smem (u32): Qu[128*36] Ku[2][64*36] Vu[2][64*36] Pu[128*36] Ms(f32)[128*68]
#define AQ_OFF 0
#define AK_OFF (128 * 36)                 // + buf*2304
#define AV_OFF (256 * 36)                 // + buf*2304
#define AP_OFF (384 * 36)
#define AM_OFF (512 * 36)
#define ATTN_SMEM_U32 (512 * 36 + 128 * 68)   // 27136 u32 = 108544 B
#define NJOBS (HH * (LL / 128) * BB)          // 1024

__global__ __launch_bounds__(256, 2) void attn_f16_kernel(const float* __restrict__ mask)
{
    extern __shared__ uint32_t sh[];
    uint32_t* Qu = sh + AQ_OFF;
    uint32_t* Pu = sh + AP_OFF;
    float* Ms = (float*)(sh + AM_OFF);
    const uint32_t qu_base = smem_u32(sh) + AQ_OFF * 4;
    const uint32_t ku_base = smem_u32(sh) + AK_OFF * 4;
    const uint32_t vu_base = smem_u32(sh) + AV_OFF * 4;
    const uint32_t pu_base = smem_u32(sh) + AP_OFF * 4;
    const uint32_t ms_base = smem_u32(sh) + AM_OFF * 4;

    const int tid = threadIdx.x;
    const int lane = tid & 31;
    const int w = tid >> 5;
    const int g = lane >> 2;
    const int t = lane & 3;

    const int q8 = lane >> 3, l8 = lane & 7;
    const uint32_t a_lane = (uint32_t)(((q8 & 1) * 8 + l8) * 144 + (q8 >> 1) * 16);
    const uint32_t b_lane = (uint32_t)(((q8 >> 1) * 8 + l8) * 144 + (q8 & 1) * 16);

    const int kvrow = tid >> 2;                 // 0..63
    const int kvsb = (tid & 3) * 2;             // seg base
    const int mrow = tid >> 4;                  // mask row base 0..15
    const int mseg = tid & 15;                  // mask seg 0..15

    for (int job = blockIdx.x; job < NJOBS; job += gridDim.x) {
        const int h = job & 15;
        const int q0 = ((job >> 4) & 15) * 128;
        const int b = job >> 8;

        // stage Q tile (fp16, pre-scaled)
        {
            int row = tid >> 1, sb = (tid & 1) * 4;
#pragma unroll
            for (int i = 0; i < 4; i++) {
                uint4 u = *(const uint4*)&d_q16[(((size_t)(b * LL + q0 + row)) * HH + h) * DD + (sb + i) * 8];
                *(uint4*)&Qu[row * 36 + (sb + i) * 4] = u;
            }
        }

        float o[4][2][4];
#pragma unroll
        for (int mt = 0; mt < 4; mt++)
#pragma unroll
            for (int nt = 0; nt < 2; nt++)
#pragma unroll
                for (int j = 0; j < 4; j++) o[mt][nt][j] = 0.f;

        float m_run[2] = {-1e30f, -1e30f};
        float l_run[2] = {0.f, 0.f};

        // prologue: prefetch tile0, STS into buf0, issue mask0
        uint4 kr[2], vr[2];
#pragma unroll
        for (int i = 0; i < 2; i++) {
            kr[i] = *(const uint4*)&d_k16[(((size_t)(b * LL + kvrow)) * HH + h) * DD + (kvsb + i) * 8];
            vr[i] = *(const uint4*)&d_vt16[(((size_t)(b * HH + h)) * DD + kvrow) * LL + (kvsb + i) * 8];
        }
        {
            uint32_t* Ku0 = sh + AK_OFF;
            uint32_t* Vu0 = sh + AV_OFF;
#pragma unroll
            for (int i = 0; i < 2; i++) {
                *(uint4*)&Ku0[kvrow * 36 + (kvsb + i) * 4] = kr[i];
                *(uint4*)&Vu0[kvrow * 36 + (kvsb + i) * 4] = vr[i];
            }
        }
#pragma unroll
        for (int i = 0; i < 8; i++) {
            int r = mrow + i * 16;
            CP16(ms_base + r * (68 * 4) + mseg * 16,
                 &mask[((size_t)(b * LL + q0 + r)) * LL + mseg * 4]);
        }
        CP_COMMIT();
        __syncthreads();

        for (int it = 0; it < LL / 64; it++) {
            const int k0 = it * 64;
            const int cur = it & 1;
            const bool more = (it + 1) < LL / 64;

            if (more) {
#pragma unroll
                for (int i = 0; i < 2; i++) {
                    kr[i] = *(const uint4*)&d_k16[(((size_t)(b * LL + k0 + 64 + kvrow)) * HH + h) * DD + (kvsb + i) * 8];
                    vr[i] = *(const uint4*)&d_vt16[(((size_t)(b * HH + h)) * DD + kvrow) * LL + k0 + 64 + (kvsb + i) * 8];
                }
            }

            // S = Q @ K^T from Ku[cur]
            float s[8][4];
#pragma unroll
            for (int nt = 0; nt < 8; nt++)
#pragma unroll
                for (int j = 0; j < 4; j++) s[nt][j] = 0.f;

            const uint32_t aqb = qu_base + (uint32_t)(w * 16) * 144 + a_lane;
            const uint32_t bkb = ku_base + (uint32_t)cur * (2304 * 4) + b_lane;
#pragma unroll
            for (int kk = 0; kk < 4; kk++) {
                const uint32_t kb = kk * 32;
                uint32_t a0, a1, a2, a3;
                LDSM4(a0, a1, a2, a3, aqb + kb);
                uint32_t bfr[8][2];
#pragma unroll
                for (int p = 0; p < 4; p++)
                    LDSM4(bfr[2 * p][0], bfr[2 * p][1], bfr[2 * p + 1][0], bfr[2 * p + 1][1],
                          bkb + (uint32_t)(p * 16) * 144 + kb);
#pragma unroll
                for (int nt = 0; nt < 8; nt++)
                    mma_f16(s[nt], a0, a1, a2, a3, bfr[nt][0], bfr[nt][1]);
            }

            CP_WAIT0();
            __syncthreads();   // mask tile fully landed

            // add mask, online row-max, exp, rowsum, P->fp16
            {
                const float* mp0 = Ms + (w * 16 + g) * 68;
                const float* mp1 = mp0 + 8 * 68;
#pragma unroll
                for (int nt = 0; nt < 8; nt++) {
                    float2 m0 = *(const float2*)&mp0[nt * 8 + 2 * t];
                    float2 m1 = *(const float2*)&mp1[nt * 8 + 2 * t];
                    s[nt][0] += m0.x; s[nt][1] += m0.y;
                    s[nt][2] += m1.x; s[nt][3] += m1.y;
                }
                float mx[2] = {-1e30f, -1e30f};
#pragma unroll
                for (int nt = 0; nt < 8; nt++) {
                    mx[0] = fmaxf(mx[0], fmaxf(s[nt][0], s[nt][1]));
                    mx[1] = fmaxf(mx[1], fmaxf(s[nt][2], s[nt][3]));
                }
#pragma unroll
                for (int i = 0; i < 2; i++) {
                    mx[i] = fmaxf(mx[i], __shfl_xor_sync(0xffffffffu, mx[i], 1));
                    mx[i] = fmaxf(mx[i], __shfl_xor_sync(0xffffffffu, mx[i], 2));
                }
                float m_new[2], corr[2], sum[2] = {0.f, 0.f};
#pragma unroll
                for (int i = 0; i < 2; i++) {
                    m_new[i] = fmaxf(m_run[i], mx[i]);
                    corr[i] = __expf(m_run[i] - m_new[i]);
                    m_run[i] = m_new[i];
                }
#pragma unroll
                for (int nt = 0; nt < 8; nt++) {
                    s[nt][0] = __expf(s[nt][0] - m_new[0]);
                    s[nt][1] = __expf(s[nt][1] - m_new[0]);
                    s[nt][2] = __expf(s[nt][2] - m_new[1]);
                    s[nt][3] = __expf(s[nt][3] - m_new[1]);
                    sum[0] += s[nt][0] + s[nt][1];
                    sum[1] += s[nt][2] + s[nt][3];
                }
#pragma unroll
                for (int i = 0; i < 2; i++) {
                    sum[i] += __shfl_xor_sync(0xffffffffu, sum[i], 1);
                    sum[i] += __shfl_xor_sync(0xffffffffu, sum[i], 2);
                    l_run[i] = l_run[i] * corr[i] + sum[i];
                }
                int r = w * 16 + g;
#pragma unroll
                for (int nt = 0; nt < 8; nt++) {
                    Pu[r * 36 + nt * 4 + t] = pack2(s[nt][0], s[nt][1]);
                    Pu[(r + 8) * 36 + nt * 4 + t] = pack2(s[nt][2], s[nt][3]);
                }
                __syncwarp();
                float cq[2][2];
#pragma unroll
                for (int nt = 0; nt < 2; nt++)
#pragma unroll
                    for (int j = 0; j < 2; j++)
                        cq[nt][j] = __shfl_sync(0xffffffffu, corr[nt], (2 * t + j) * 4);
#pragma unroll
                for (int mt = 0; mt < 4; mt++)
#pragma unroll
                    for (int nt = 0; nt < 2; nt++) {
                        o[mt][nt][0] *= cq[nt][0];
                        o[mt][nt][1] *= cq[nt][1];
                        o[mt][nt][2] *= cq[nt][0];
                        o[mt][nt][3] *= cq[nt][1];
                    }
            }

            // O^T += V^T @ P^T from Vu[cur]
            const uint32_t avb = vu_base + (uint32_t)cur * (2304 * 4) + a_lane;
            const uint32_t bpb = pu_base + (uint32_t)(w * 16) * 144 + b_lane;
#pragma unroll
            for (int kk = 0; kk < 4; kk++) {
                const uint32_t kb = kk * 32;
                uint32_t bfr[2][2];
                LDSM4(bfr[0][0], bfr[0][1], bfr[1][0], bfr[1][1], bpb + kb);
#pragma unroll
                for (int mt = 0; mt < 4; mt++) {
                    uint32_t a0, a1, a2, a3;
                    LDSM4(a0, a1, a2, a3, avb + (uint32_t)(mt * 16) * 144 + kb);
#pragma unroll
                    for (int nt = 0; nt < 2; nt++)
                        mma_f16(o[mt][nt], a0, a1, a2, a3, bfr[nt][0], bfr[nt][1]);
                }
            }

            // stage next K/V into the other buffer
            if (more) {
                uint32_t* Kn = sh + AK_OFF + (cur ^ 1) * 2304;
                uint32_t* Vn = sh + AV_OFF + (cur ^ 1) * 2304;
#pragma unroll
                for (int i = 0; i < 2; i++) {
                    *(uint4*)&Kn[kvrow * 36 + (kvsb + i) * 4] = kr[i];
                    *(uint4*)&Vn[kvrow * 36 + (kvsb + i) * 4] = vr[i];
                }
            }
            __syncthreads();   // tile done

            if (more) {
#pragma unroll
                for (int i = 0; i < 8; i++) {
                    int r = mrow + i * 16;
                    CP16(ms_base + r * (68 * 4) + mseg * 16,
                         &mask[((size_t)(b * LL + q0 + r)) * LL + k0 + 64 + mseg * 4]);
                }
                CP_COMMIT();
            }
        }

        // epilogue: normalize, gate, store fp16 for out-proj
        float inv[2][2];
#pragma unroll
        for (int nt = 0; nt < 2; nt++)
#pragma unroll
            for (int j = 0; j < 2; j++)
                inv[nt][j] = 1.0f / __shfl_sync(0xffffffffu, l_run[nt], (2 * t + j) * 4);

#pragma unroll
        for (int nt = 0; nt < 2; nt++)
#pragma unroll
            for (int j = 0; j < 2; j++) {
                int q = q0 + w * 16 + nt * 8 + 2 * t + j;
                size_t gbase = (size_t)(b * LL + q) * NQKV + h * 128 + 64;
                size_t obase = (((size_t)(b * LL + q)) * HH + h) * DD;
#pragma unroll
                for (int mt = 0; mt < 4; mt++) {
                    int d0 = mt * 16 + g;
                    float g0 = d_qkv_buf[gbase + d0];
                    float g1 = d_qkv_buf[gbase + d0 + 8];
                    float v0 = o[mt][nt][j] * inv[nt][j] * (1.0f / (1.0f + __expf(-g0)));
                    float v1 = o[mt][nt][j + 2] * inv[nt][j] * (1.0f / (1.0f + __expf(-g1)));
                    d_ao16[obase + d0]     = __float2half(v0);
                    d_ao16[obase + d0 + 8] = __float2half(v1);
                }
            }
        // no barrier needed: next job's smem writes are ordered after this
        // job's final tile barrier, which every warp has passed.
    }
}

// ---------------------------------------------------------------------------
extern "C" void kernel_launch(void* const* d_in, const int* in_sizes, int n_in,
                              void* d_out, int out_size)
{
    (void)in_sizes; (void)n_in; (void)out_size;
    const float* h    = (const float*)d_in[0];
    const float* cosb = (const float*)d_in[1];
    const float* sinb = (const float*)d_in[2];
    const float* mask = (const float*)d_in[3];
    const float* wq   = (const float*)d_in[4];
    const float* wk   = (const float*)d_in[5];
    const float* wv   = (const float*)d_in[6];
    const float* wo   = (const float*)d_in[7];
    const float* qnw  = (const float*)d_in[8];
    const float* knw  = (const float*)d_in[9];
    float* out = (float*)d_out;

    float* qkv;
    __half *h16, *wqkv16t, *wo16t, *ao16;
    cudaGetSymbolAddress((void**)&qkv, d_qkv_buf);
    cudaGetSymbolAddress((void**)&h16, d_h16);
    cudaGetSymbolAddress((void**)&wqkv16t, d_wqkv16t);
    cudaGetSymbolAddress((void**)&wo16t, d_wo16t);
    cudaGetSymbolAddress((void**)&ao16, d_ao16);

    const int M = BB * LL;   // 8192

    static int nsm = 0;
    if (nsm == 0) {
        cudaDeviceGetAttribute(&nsm, cudaDevAttrMultiProcessorCount, 0);
        if (nsm <= 0) nsm = 148;
    }
    int attn_grid = nsm * 2;
    if (attn_grid > NJOBS) attn_grid = NJOBS;

    // h -> fp16
    {
        int n8 = (M * EE) / 8;
        cvt_h16_kernel<<<(n8 + 255) / 256, 256>>>((const float4*)h, (uint4*)h16, n8);
    }
    // all weight transposes in one launch
    transpose_all_kernel<<<dim3(64, 32, 4), dim3(32, 8)>>>(wq, wk, wv, wo);

    cudaFuncSetAttribute(h16_gemm, cudaFuncAttributeMaxDynamicSharedMemorySize,
                         GEMM_SMEM_BYTES);

    // merged QKV projection
    h16_gemm<<<dim3(NQKV / 128, M / 128), 256, GEMM_SMEM_BYTES>>>(
        h16, wqkv16t, qkv, M, NQKV, EE);

    // RMSNorm + partial RoPE (q+k per warp)
    {
        int warps = BB * LL * HH;
        int blocks = (warps * 32 + 255) / 256;
        norm_rope_kernel<<<blocks, 256>>>(cosb, sinb, qnw, knw);
    }
    // per-head V transpose
    vtrans_kernel<<<dim3(LL / 32, DD / 32, BB * HH), dim3(32, 8)>>>();

    // persistent fused fp16 flash attention + gate
    {
        int smem = ATTN_SMEM_U32 * 4;
        cudaFuncSetAttribute(attn_f16_kernel, cudaFuncAttributeMaxDynamicSharedMemorySize, smem);
        attn_f16_kernel<<<attn_grid, 256, smem>>>(mask);
    }

    // output projection
    h16_gemm<<<dim3(EE / 128, M / 128), 256, GEMM_SMEM_BYTES>>>(
        ao16, wo16t, out, M, EE, HH * DD);
}

// round 17
// speedup vs baseline: 1.0726x; 1.0726x over previous
#include <cuda_runtime.h>
#include <cuda_fp16.h>
#include <cstdint>

#define BB 4
#define LL 2048
#define EE 1024
#define HH 16
#define DD 64
#define NQKV 4096   // merged QKV output columns: 2048 q|gate, 1024 k, 1024 v

// ---------------- scratch ----------------------------------------------------
__device__ float d_qkv_buf[(size_t)BB * LL * NQKV];        // merged f32 QKV out
__device__ __half d_h16   [(size_t)BB * LL * EE];          // fp16 h
__device__ __half d_wqkv16t[(size_t)NQKV * EE];            // [N][K] fp16 (wq|wk|wv)
__device__ __half d_wo16t [(size_t)EE * HH * DD];
__device__ __half d_q16   [(size_t)BB * LL * HH * DD];     // normed+rope q * 0.125
__device__ __half d_k16   [(size_t)BB * LL * HH * DD];     // normed+rope k
__device__ __half d_vt16  [(size_t)BB * HH * DD * LL];     // V^T per head: [b,h,d,l]
__device__ __half d_ao16  [(size_t)BB * LL * HH * DD];     // gated attn out fp16

// ---------------- helpers ----------------------------------------------------
__device__ __forceinline__ void mma_f16(float* d,
    uint32_t a0, uint32_t a1, uint32_t a2, uint32_t a3,
    uint32_t b0, uint32_t b1)
{
    asm("mma.sync.aligned.m16n8k16.row.col.f32.f16.f16.f32 "
        "{%0,%1,%2,%3}, {%4,%5,%6,%7}, {%8,%9}, {%0,%1,%2,%3};"
        : "+f"(d[0]), "+f"(d[1]), "+f"(d[2]), "+f"(d[3])
        : "r"(a0), "r"(a1), "r"(a2), "r"(a3), "r"(b0), "r"(b1));
}

__device__ __forceinline__ uint32_t smem_u32(const void* p) {
    uint32_t a;
    asm("{ .reg .u64 t; cvta.to.shared.u64 t, %1; cvt.u32.u64 %0, t; }" : "=r"(a) : "l"(p));
    return a;
}

__device__ __forceinline__ uint32_t pack2(float x, float y) {
    __half2 h = __floats2half2_rn(x, y);
    return *(uint32_t*)&h;
}

#define LDSM4(d0, d1, d2, d3, addr) \
    asm volatile("ldmatrix.sync.aligned.m8n8.x4.shared.b16 {%0,%1,%2,%3}, [%4];" \
        : "=r"(d0), "=r"(d1), "=r"(d2), "=r"(d3) : "r"(addr))

#define CP16(dst, src) \
    asm volatile("cp.async.cg.shared.global [%0], [%1], 16;" :: "r"(dst), "l"(src))
#define CP_COMMIT() asm volatile("cp.async.commit_group;")
#define CP_WAIT2()  asm volatile("cp.async.wait_group 2;" ::: "memory")
#define CP_WAIT0()  asm volatile("cp.async.wait_group 0;" ::: "memory")

// ---------------- f32 -> f16 elementwise (8 elems/thread) --------------------
__global__ __launch_bounds__(256) void cvt_h16_kernel(
    const float4* __restrict__ src, uint4* __restrict__ dst, int n8)
{
    int i = blockIdx.x * blockDim.x + threadIdx.x;
    if (i < n8) {
        float4 a = src[2 * i], b = src[2 * i + 1];
        dst[i] = make_uint4(pack2(a.x, a.y), pack2(a.z, a.w),
                            pack2(b.x, b.y), pack2(b.z, b.w));
    }
}

// ---------------- merged weight transpose + cvt (4 matrices, one launch) -----
__global__ __launch_bounds__(256) void transpose_all_kernel(
    const float* __restrict__ wq, const float* __restrict__ wk,
    const float* __restrict__ wv, const float* __restrict__ wo)
{
    __shared__ float sm[32][33];
    const float* in;
    __half* out;
    int N;
    switch (blockIdx.z) {
        case 0: in = wq; out = d_wqkv16t;                      N = 2048; break;
        case 1: in = wk; out = d_wqkv16t + (size_t)2048 * EE;  N = 1024; break;
        case 2: in = wv; out = d_wqkv16t + (size_t)3072 * EE;  N = 1024; break;
        default: in = wo; out = d_wo16t;                       N = 1024; break;
    }
    const int K = EE;
    int n0 = blockIdx.x * 32, k0 = blockIdx.y * 32;
    if (n0 >= N) return;
    int tx = threadIdx.x, ty = threadIdx.y;
#pragma unroll
    for (int i = 0; i < 4; i++)
        sm[ty + i * 8][tx] = in[(size_t)(k0 + ty + i * 8) * N + n0 + tx];
    __syncthreads();
#pragma unroll
    for (int i = 0; i < 4; i++)
        out[(size_t)(n0 + ty + i * 8) * K + k0 + tx] = __float2half(sm[tx][ty + i * 8]);
}

// ---------------- per-head V transpose: qkv v-cols f32 -> vt[b,h,d,l] f16 ----
__global__ __launch_bounds__(256) void vtrans_kernel()
{
    __shared__ float sm[32][33];
    int bh = blockIdx.z;                    // b*16 + h
    int b = bh >> 4, h = bh & 15;
    int d0 = blockIdx.y * 32, l0 = blockIdx.x * 32;
    int tx = threadIdx.x, ty = threadIdx.y;
#pragma unroll
    for (int i = 0; i < 4; i++)
        sm[ty + i * 8][tx] =
            d_qkv_buf[(size_t)(b * LL + l0 + ty + i * 8) * NQKV + 3072 + h * DD + d0 + tx];
    __syncthreads();
#pragma unroll
    for (int i = 0; i < 4; i++)
        d_vt16[((size_t)bh * DD + d0 + ty + i * 8) * LL + l0 + tx] =
            __float2half(sm[tx][ty + i * 8]);
}

// ---------------- fp16 GEMM: C[M,N] = A[M,K] @ Bt[N,K]^T ---------------------
#define GSTR 36
#define GSTAGE_U32 (2 * 128 * GSTR)              // 9216 u32 = 36864 B
#define GEMM_SMEM_BYTES (3 * GSTAGE_U32 * 4)     // 110592 B

__global__ __launch_bounds__(256, 2) void h16_gemm(
    const __half* __restrict__ A, const __half* __restrict__ Bt,
    float* __restrict__ C, int M, int N, int K)
{
    extern __shared__ uint32_t sh[];
    const uint32_t sbase = smem_u32(sh);

    const int tid = threadIdx.x;
    const int lane = tid & 31;
    const int w = tid >> 5;
    const int t = lane & 3;
    const int wm = w & 3;
    const int wn = w >> 2;
    const int rowBase = blockIdx.y * 128;
    const int colBase = blockIdx.x * 128;

    const int q8 = lane >> 3, l8 = lane & 7;
    const uint32_t a_lane = (uint32_t)(((q8 & 1) * 8 + l8) * 144 + (q8 >> 1) * 16);
    const uint32_t b_lane = (uint32_t)(((q8 >> 1) * 8 + l8) * 144 + (q8 & 1) * 16);

    const int crow = tid >> 1;
    const int csb = (tid & 1) * 4;

    const int nch = K / 64;

    auto issue = [&](int c) {
        if (c < nch) {
            const uint32_t st = sbase + (c % 3) * (GSTAGE_U32 * 4);
            const int k0 = c * 64;
#pragma unroll
            for (int i = 0; i < 4; i++)
                CP16(st + crow * 144 + (csb + i) * 16,
                     &A[(size_t)(rowBase + crow) * K + k0 + (csb + i) * 8]);
            const uint32_t bst = st + 128 * 144;
#pragma unroll
            for (int i = 0; i < 4; i++)
                CP16(bst + crow * 144 + (csb + i) * 16,
                     &Bt[(size_t)(colBase + crow) * K + k0 + (csb + i) * 8]);
        }
        CP_COMMIT();
    };

    float acc[2][8][4];
#pragma unroll
    for (int mt = 0; mt < 2; mt++)
#pragma unroll
        for (int nt = 0; nt < 8; nt++)
#pragma unroll
            for (int j = 0; j < 4; j++) acc[mt][nt][j] = 0.f;

    issue(0); issue(1); issue(2);

    for (int c = 0; c < nch; c++) {
        CP_WAIT2();
        __syncthreads();
        const uint32_t st = sbase + (c % 3) * (GSTAGE_U32 * 4);
        const uint32_t abase = st + (uint32_t)(wm * 32) * 144 + a_lane;
        const uint32_t bbase = st + 128 * 144 + (uint32_t)(wn * 64) * 144 + b_lane;

#pragma unroll
        for (int kk = 0; kk < 4; kk++) {
            const uint32_t kb = kk * 32;
            uint32_t a[2][4];
            LDSM4(a[0][0], a[0][1], a[0][2], a[0][3], abase + kb);
            LDSM4(a[1][0], a[1][1], a[1][2], a[1][3], abase + 16 * 144 + kb);
            uint32_t b[8][2];
#pragma unroll
            for (int p = 0; p < 4; p++)
                LDSM4(b[2 * p][0], b[2 * p][1], b[2 * p + 1][0], b[2 * p + 1][1],
                      bbase + (uint32_t)(p * 16) * 144 + kb);
#pragma unroll
            for (int mt = 0; mt < 2; mt++)
#pragma unroll
                for (int nt = 0; nt < 8; nt++)
                    mma_f16(acc[mt][nt], a[mt][0], a[mt][1], a[mt][2], a[mt][3],
                            b[nt][0], b[nt][1]);
        }
        __syncthreads();
        issue(c + 3);
    }

    const int g = lane >> 2;
#pragma unroll
    for (int mt = 0; mt < 2; mt++) {
        int row = rowBase + wm * 32 + mt * 16 + g;
#pragma unroll
        for (int nt = 0; nt < 8; nt++) {
            int col = colBase + wn * 64 + nt * 8 + 2 * t;
            *(float2*)&C[(size_t)row * N + col] = make_float2(acc[mt][nt][0], acc[mt][nt][1]);
            *(float2*)&C[(size_t)(row + 8) * N + col] = make_float2(acc[mt][nt][2], acc[mt][nt][3]);
        }
    }
}

// ---------------- RMSNorm + partial RoPE -> fp16 q/k (q+k per warp) ----------
__global__ __launch_bounds__(256) void norm_rope_kernel(
    const float* __restrict__ cosb, const float* __restrict__ sinb,
    const float* __restrict__ qw, const float* __restrict__ kw)
{
    int row = (blockIdx.x * blockDim.x + threadIdx.x) >> 5;   // (bl, h)
    int lane = threadIdx.x & 31;
    if (row >= BB * LL * HH) return;
    int h = row % HH;
    int bl = row / HH;

    float c0 = 1.f, s0 = 0.f, c1 = 1.f, s1 = 0.f;
    if (lane < 24) {
        const float* cp = cosb + (size_t)bl * DD;
        const float* sp = sinb + (size_t)bl * DD;
        c0 = cp[lane];      s0 = sp[lane];
        c1 = cp[lane + 32]; s1 = sp[lane + 32];
    }

    // ---- q ----
    {
        const float* ptr = d_qkv_buf + (size_t)bl * NQKV + h * 128;
        float x0 = ptr[lane];
        float x1 = ptr[lane + 32];
        float ss = x0 * x0 + x1 * x1;
#pragma unroll
        for (int o = 16; o; o >>= 1) ss += __shfl_xor_sync(0xffffffffu, ss, o);
        float r = rsqrtf(ss * (1.0f / 64.0f) + 1e-6f);
        x0 = x0 * r * qw[lane];
        x1 = x1 * r * qw[lane + 32];
        float r0 = (x0 * c0 - x1 * s0) * 0.125f;
        float r1 = (x1 * c1 + x0 * s1) * 0.125f;
        __half* dst = d_q16 + ((size_t)bl * HH + h) * DD;
        dst[lane]      = __float2half(r0);
        dst[lane + 32] = __float2half(r1);
    }
    // ---- k ----
    {
        const float* ptr = d_qkv_buf + (size_t)bl * NQKV + 2048 + h * DD;
        float x0 = ptr[lane];
        float x1 = ptr[lane + 32];
        float ss = x0 * x0 + x1 * x1;
#pragma unroll
        for (int o = 16; o; o >>= 1) ss += __shfl_xor_sync(0xffffffffu, ss, o);
        float r = rsqrtf(ss * (1.0f / 64.0f) + 1e-6f);
        x0 = x0 * r * kw[lane];
        x1 = x1 * r * kw[lane + 32];
        float r0 = x0 * c0 - x1 * s0;
        float r1 = x1 * c1 + x0 * s1;
        __half* dst = d_k16 + ((size_t)bl * HH + h) * DD;
        dst[lane]      = __float2half(r0);
        dst[lane + 32] = __float2half(r1);
    }
}

// ---------------- fp16 flash attention, double-buffered K/V ------------------
// (dynamic block scheduling: grid (HH, LL/128, BB) — persistent variant was
//  measured 60us slower in R16; hardware scheduler balances better)
#define AQ_OFF 0
#define AK_OFF (128 * 36)                 // + buf*2304
#define AV_OFF (256 * 36)                 // + buf*2304
#define AP_OFF (384 * 36)
#define AM_OFF (512 * 36)
#define ATTN_SMEM_U32 (512 * 36 + 128 * 68)   // 27136 u32 = 108544 B

__global__ __launch_bounds__(256, 2) void attn_f16_kernel(const float* __restrict__ mask)
{
    extern __shared__ uint32_t sh[];
    uint32_t* Qu = sh + AQ_OFF;
    uint32_t* Pu = sh + AP_OFF;
    float* Ms = (float*)(sh + AM_OFF);
    const uint32_t qu_base = smem_u32(sh) + AQ_OFF * 4;
    const uint32_t ku_base = smem_u32(sh) + AK_OFF * 4;
    const uint32_t vu_base = smem_u32(sh) + AV_OFF * 4;
    const uint32_t pu_base = smem_u32(sh) + AP_OFF * 4;
    const uint32_t ms_base = smem_u32(sh) + AM_OFF * 4;

    const int tid = threadIdx.x;
    const int lane = tid & 31;
    const int w = tid >> 5;
    const int g = lane >> 2;
    const int t = lane & 3;
    const int h = blockIdx.x;
    const int q0 = blockIdx.y * 128;
    const int b = blockIdx.z;

    const int q8 = lane >> 3, l8 = lane & 7;
    const uint32_t a_lane = (uint32_t)(((q8 & 1) * 8 + l8) * 144 + (q8 >> 1) * 16);
    const uint32_t b_lane = (uint32_t)(((q8 >> 1) * 8 + l8) * 144 + (q8 & 1) * 16);

    // stage Q tile (fp16, pre-scaled)
    {
        int row = tid >> 1, sb = (tid & 1) * 4;
#pragma unroll
        for (int i = 0; i < 4; i++) {
            uint4 u = *(const uint4*)&d_q16[(((size_t)(b * LL + q0 + row)) * HH + h) * DD + (sb + i) * 8];
            *(uint4*)&Qu[row * 36 + (sb + i) * 4] = u;
        }
    }

    float o[4][2][4];
#pragma unroll
    for (int mt = 0; mt < 4; mt++)
#pragma unroll
        for (int nt = 0; nt < 2; nt++)
#pragma unroll
            for (int j = 0; j < 4; j++) o[mt][nt][j] = 0.f;

    float m_run[2] = {-1e30f, -1e30f};
    float l_run[2] = {0.f, 0.f};

    const int kvrow = tid >> 2;                 // 0..63
    const int kvsb = (tid & 3) * 2;             // seg base
    const int mrow = tid >> 4;                  // mask row base 0..15
    const int mseg = tid & 15;                  // mask seg 0..15

    // prologue: prefetch tile0, STS into buf0, issue mask0
    uint4 kr[2], vr[2];
#pragma unroll
    for (int i = 0; i < 2; i++) {
        kr[i] = *(const uint4*)&d_k16[(((size_t)(b * LL + kvrow)) * HH + h) * DD + (kvsb + i) * 8];
        vr[i] = *(const uint4*)&d_vt16[(((size_t)(b * HH + h)) * DD + kvrow) * LL + (kvsb + i) * 8];
    }
    {
        uint32_t* Ku0 = sh + AK_OFF;
        uint32_t* Vu0 = sh + AV_OFF;
#pragma unroll
        for (int i = 0; i < 2; i++) {
            *(uint4*)&Ku0[kvrow * 36 + (kvsb + i) * 4] = kr[i];
            *(uint4*)&Vu0[kvrow * 36 + (kvsb + i) * 4] = vr[i];
        }
    }
#pragma unroll
    for (int i = 0; i < 8; i++) {
        int r = mrow + i * 16;
        CP16(ms_base + r * (68 * 4) + mseg * 16,
             &mask[((size_t)(b * LL + q0 + r)) * LL + mseg * 4]);
    }
    CP_COMMIT();
    __syncthreads();

    for (int it = 0; it < LL / 64; it++) {
        const int k0 = it * 64;
        const int cur = it & 1;
        const bool more = (it + 1) < LL / 64;

        if (more) {
#pragma unroll
            for (int i = 0; i < 2; i++) {
                kr[i] = *(const uint4*)&d_k16[(((size_t)(b * LL + k0 + 64 + kvrow)) * HH + h) * DD + (kvsb + i) * 8];
                vr[i] = *(const uint4*)&d_vt16[(((size_t)(b * HH + h)) * DD + kvrow) * LL + k0 + 64 + (kvsb + i) * 8];
            }
        }

        // S = Q @ K^T from Ku[cur]
        float s[8][4];
#pragma unroll
        for (int nt = 0; nt < 8; nt++)
#pragma unroll
            for (int j = 0; j < 4; j++) s[nt][j] = 0.f;

        const uint32_t aqb = qu_base + (uint32_t)(w * 16) * 144 + a_lane;
        const uint32_t bkb = ku_base + (uint32_t)cur * (2304 * 4) + b_lane;
#pragma unroll
        for (int kk = 0; kk < 4; kk++) {
            const uint32_t kb = kk * 32;
            uint32_t a0, a1, a2, a3;
            LDSM4(a0, a1, a2, a3, aqb + kb);
            uint32_t bfr[8][2];
#pragma unroll
            for (int p = 0; p < 4; p++)
                LDSM4(bfr[2 * p][0], bfr[2 * p][1], bfr[2 * p + 1][0], bfr[2 * p + 1][1],
                      bkb + (uint32_t)(p * 16) * 144 + kb);
#pragma unroll
            for (int nt = 0; nt < 8; nt++)
                mma_f16(s[nt], a0, a1, a2, a3, bfr[nt][0], bfr[nt][1]);
        }

        CP_WAIT0();
        __syncthreads();   // mask tile fully landed

        // add mask, online row-max, exp, rowsum, P->fp16
        {
            const float* mp0 = Ms + (w * 16 + g) * 68;
            const float* mp1 = mp0 + 8 * 68;
#pragma unroll
            for (int nt = 0; nt < 8; nt++) {
                float2 m0 = *(const float2*)&mp0[nt * 8 + 2 * t];
                float2 m1 = *(const float2*)&mp1[nt * 8 + 2 * t];
                s[nt][0] += m0.x; s[nt][1] += m0.y;
                s[nt][2] += m1.x; s[nt][3] += m1.y;
            }
            float mx[2] = {-1e30f, -1e30f};
#pragma unroll
            for (int nt = 0; nt < 8; nt++) {
                mx[0] = fmaxf(mx[0], fmaxf(s[nt][0], s[nt][1]));
                mx[1] = fmaxf(mx[1], fmaxf(s[nt][2], s[nt][3]));
            }
#pragma unroll
            for (int i = 0; i < 2; i++) {
                mx[i] = fmaxf(mx[i], __shfl_xor_sync(0xffffffffu, mx[i], 1));
                mx[i] = fmaxf(mx[i], __shfl_xor_sync(0xffffffffu, mx[i], 2));
            }
            float m_new[2], corr[2], sum[2] = {0.f, 0.f};
#pragma unroll
            for (int i = 0; i < 2; i++) {
                m_new[i] = fmaxf(m_run[i], mx[i]);
                corr[i] = __expf(m_run[i] - m_new[i]);
                m_run[i] = m_new[i];
            }
#pragma unroll
            for (int nt = 0; nt < 8; nt++) {
                s[nt][0] = __expf(s[nt][0] - m_new[0]);
                s[nt][1] = __expf(s[nt][1] - m_new[0]);
                s[nt][2] = __expf(s[nt][2] - m_new[1]);
                s[nt][3] = __expf(s[nt][3] - m_new[1]);
                sum[0] += s[nt][0] + s[nt][1];
                sum[1] += s[nt][2] + s[nt][3];
            }
#pragma unroll
            for (int i = 0; i < 2; i++) {
                sum[i] += __shfl_xor_sync(0xffffffffu, sum[i], 1);
                sum[i] += __shfl_xor_sync(0xffffffffu, sum[i], 2);
                l_run[i] = l_run[i] * corr[i] + sum[i];
            }
            int r = w * 16 + g;
#pragma unroll
            for (int nt = 0; nt < 8; nt++) {
                Pu[r * 36 + nt * 4 + t] = pack2(s[nt][0], s[nt][1]);
                Pu[(r + 8) * 36 + nt * 4 + t] = pack2(s[nt][2], s[nt][3]);
            }
            __syncwarp();
            float cq[2][2];
#pragma unroll
            for (int nt = 0; nt < 2; nt++)
#pragma unroll
                for (int j = 0; j < 2; j++)
                    cq[nt][j] = __shfl_sync(0xffffffffu, corr[nt], (2 * t + j) * 4);
#pragma unroll
            for (int mt = 0; mt < 4; mt++)
#pragma unroll
                for (int nt = 0; nt < 2; nt++) {
                    o[mt][nt][0] *= cq[nt][0];
                    o[mt][nt][1] *= cq[nt][1];
                    o[mt][nt][2] *= cq[nt][0];
                    o[mt][nt][3] *= cq[nt][1];
                }
        }

        // O^T += V^T @ P^T from Vu[cur]
        const uint32_t avb = vu_base + (uint32_t)cur * (2304 * 4) + a_lane;
        const uint32_t bpb = pu_base + (uint32_t)(w * 16) * 144 + b_lane;
#pragma unroll
        for (int kk = 0; kk < 4; kk++) {
            const uint32_t kb = kk * 32;
            uint32_t bfr[2][2];
            LDSM4(bfr[0][0], bfr[0][1], bfr[1][0], bfr[1][1], bpb + kb);
#pragma unroll
            for (int mt = 0; mt < 4; mt++) {
                uint32_t a0, a1, a2, a3;
                LDSM4(a0, a1, a2, a3, avb + (uint32_t)(mt * 16) * 144 + kb);
#pragma unroll
                for (int nt = 0; nt < 2; nt++)
                    mma_f16(o[mt][nt], a0, a1, a2, a3, bfr[nt][0], bfr[nt][1]);
            }
        }

        // stage next K/V into the other buffer
        if (more) {
            uint32_t* Kn = sh + AK_OFF + (cur ^ 1) * 2304;
            uint32_t* Vn = sh + AV_OFF + (cur ^ 1) * 2304;
#pragma unroll
            for (int i = 0; i < 2; i++) {
                *(uint4*)&Kn[kvrow * 36 + (kvsb + i) * 4] = kr[i];
                *(uint4*)&Vn[kvrow * 36 + (kvsb + i) * 4] = vr[i];
            }
        }
        __syncthreads();   // tile done

        if (more) {
#pragma unroll
            for (int i = 0; i < 8; i++) {
                int r = mrow + i * 16;
                CP16(ms_base + r * (68 * 4) + mseg * 16,
                     &mask[((size_t)(b * LL + q0 + r)) * LL + k0 + 64 + mseg * 4]);
            }
            CP_COMMIT();
        }
    }

    // epilogue: normalize, gate, store fp16 for out-proj
    float inv[2][2];
#pragma unroll
    for (int nt = 0; nt < 2; nt++)
#pragma unroll
        for (int j = 0; j < 2; j++)
            inv[nt][j] = 1.0f / __shfl_sync(0xffffffffu, l_run[nt], (2 * t + j) * 4);

#pragma unroll
    for (int nt = 0; nt < 2; nt++)
#pragma unroll
        for (int j = 0; j < 2; j++) {
            int q = q0 + w * 16 + nt * 8 + 2 * t + j;
            size_t gbase = (size_t)(b * LL + q) * NQKV + h * 128 + 64;
            size_t obase = (((size_t)(b * LL + q)) * HH + h) * DD;
#pragma unroll
            for (int mt = 0; mt < 4; mt++) {
                int d0 = mt * 16 + g;
                float g0 = d_qkv_buf[gbase + d0];
                float g1 = d_qkv_buf[gbase + d0 + 8];
                float v0 = o[mt][nt][j] * inv[nt][j] * (1.0f / (1.0f + __expf(-g0)));
                float v1 = o[mt][nt][j + 2] * inv[nt][j] * (1.0f / (1.0f + __expf(-g1)));
                d_ao16[obase + d0]     = __float2half(v0);
                d_ao16[obase + d0 + 8] = __float2half(v1);
            }
        }
}

// ---------------------------------------------------------------------------
extern "C" void kernel_launch(void* const* d_in, const int* in_sizes, int n_in,
                              void* d_out, int out_size)
{
    (void)in_sizes; (void)n_in; (void)out_size;
    const float* h    = (const float*)d_in[0];
    const float* cosb = (const float*)d_in[1];
    const float* sinb = (const float*)d_in[2];
    const float* mask = (const float*)d_in[3];
    const float* wq   = (const float*)d_in[4];
    const float* wk   = (const float*)d_in[5];
    const float* wv   = (const float*)d_in[6];
    const float* wo   = (const float*)d_in[7];
    const float* qnw  = (const float*)d_in[8];
    const float* knw  = (const float*)d_in[9];
    float* out = (float*)d_out;

    float* qkv;
    __half *h16, *wqkv16t, *wo16t, *ao16;
    cudaGetSymbolAddress((void**)&qkv, d_qkv_buf);
    cudaGetSymbolAddress((void**)&h16, d_h16);
    cudaGetSymbolAddress((void**)&wqkv16t, d_wqkv16t);
    cudaGetSymbolAddress((void**)&wo16t, d_wo16t);
    cudaGetSymbolAddress((void**)&ao16, d_ao16);

    const int M = BB * LL;   // 8192

    // h -> fp16
    {
        int n8 = (M * EE) / 8;
        cvt_h16_kernel<<<(n8 + 255) / 256, 256>>>((const float4*)h, (uint4*)h16, n8);
    }
    // all weight transposes in one launch
    transpose_all_kernel<<<dim3(64, 32, 4), dim3(32, 8)>>>(wq, wk, wv, wo);

    cudaFuncSetAttribute(h16_gemm, cudaFuncAttributeMaxDynamicSharedMemorySize,
                         GEMM_SMEM_BYTES);

    // merged QKV projection
    h16_gemm<<<dim3(NQKV / 128, M / 128), 256, GEMM_SMEM_BYTES>>>(
        h16, wqkv16t, qkv, M, NQKV, EE);

    // RMSNorm + partial RoPE (q+k per warp)
    {
        int warps = BB * LL * HH;
        int blocks = (warps * 32 + 255) / 256;
        norm_rope_kernel<<<blocks, 256>>>(cosb, sinb, qnw, knw);
    }
    // per-head V transpose
    vtrans_kernel<<<dim3(LL / 32, DD / 32, BB * HH), dim3(32, 8)>>>();

    // fused fp16 flash attention + gate (dynamic block scheduling)
    {
        int smem = ATTN_SMEM_U32 * 4;
        cudaFuncSetAttribute(attn_f16_kernel, cudaFuncAttributeMaxDynamicSharedMemorySize, smem);
        attn_f16_kernel<<<dim3(HH, LL / 128, BB), 256, smem>>>(mask);
    }

    // output projection
    h16_gemm<<<dim3(EE / 128, M / 128), 256, GEMM_SMEM_BYTES>>>(
        ao16, wo16t, out, M, EE, HH * DD);
}